// round 8
// baseline (speedup 1.0000x reference)
#include <cuda_runtime.h>
#include <cuda_bf16.h>

static constexpr int BATCH = 2048;
static constexpr int NSLOT = 64;
static constexpr int FEAT  = 19;
static constexpr int WPC   = 4;              // warps (=batches) per CTA
static constexpr int TPB   = 32 * WPC;       // 128
static constexpr int GRID  = BATCH / WPC;    // 512

__device__ float g_blockpart[GRID];
__device__ int   g_count = 0;                // self-resetting -> graph-replay safe

// One WARP per batch. Lane l owns rows {l, l+32} and columns {l, l+32}.
// Column p-values, taken bits and assigned-row bits are register-resident;
// only the proposal mailbox (s_ck) and the final permutation live in smem.
__global__ __launch_bounds__(TPB) void spotting_kernel(
    const float* __restrict__ y_true,
    const float* __restrict__ y_pred,
    float*       __restrict__ out)
{
    const unsigned FULL = 0xffffffffu;
    const int w = threadIdx.x >> 5;
    const int l = threadIdx.x & 31;
    const int b = blockIdx.x * WPC + w;

    __shared__ unsigned long long s_ck[WPC][NSLOT];   // proposal mailbox
    __shared__ int                s_perm[WPC][NSLOT]; // row -> column
    __shared__ float              s_wpart[WPC];
    __shared__ int                s_flag;

    const float* yt = y_true + (size_t)b * NSLOT * FEAT;
    const float* yp = y_pred + (size_t)b * NSLOT * FEAT;

    // Per-lane state: rows l and l+32; columns l and l+32.
    const float a0  = yt[l * FEAT + 0];
    const float x0  = yt[l * FEAT + 1];
    const float a1  = yt[(l + 32) * FEAT + 0];
    const float x1  = yt[(l + 32) * FEAT + 1];
    const float pc0 = yp[l * FEAT + 1];          // column l
    const float pc1 = yp[(l + 32) * FEAT + 1];   // column l+32

    s_ck[w][l]        = 0ULL;
    s_ck[w][l + 32]   = 0ULL;
    s_perm[w][l]      = l;        // defensive init (always overwritten)
    s_perm[w][l + 32] = l + 32;

    unsigned t0 = 0u, t1 = 0u;       // taken columns (bit l: col l / col l+32)
    unsigned asgLo = 0u, asgHi = 0u; // assigned rows  (bit r / bit r-32)

    __syncwarp();

    #pragma unroll 1
    for (int phase = 0; phase < 2; ++phase) {
        const bool inp0 = (phase == 0) ? (a0 > 0.5f) : (a0 <= 0.5f);
        const bool inp1 = (phase == 0) ? (a1 > 0.5f) : (a1 <= 0.5f);

        // Bounded like the reference scan (length = n). Each productive round
        // assigns >= 1 row, so this bound is never binding in practice.
        #pragma unroll 1
        for (int iter = 0; iter < NSLOT; ++iter) {
            const bool act0 = inp0 && !((asgLo >> l) & 1u);
            const bool act1 = inp1 && !((asgHi >> l) & 1u);
            unsigned m0 = __ballot_sync(FULL, act0);
            unsigned m1 = __ballot_sync(FULL, act1);
            if ((m0 | m1) == 0u) break;

            // Cooperative per-row argmax of d = 1 - |x_r - p_j| over free j.
            // d > 0 for free cols (x,p in [0,1)); key 0 excludes taken cols.
            // Positive-float bits are monotone -> reduce_max on bits == max d.
            // Lowest-j tie-break via ballot ffs == jnp.argmax first occurrence.
            #pragma unroll 1
            for (int s = 0; s < 2; ++s) {
                unsigned m = s ? m1 : m0;
                while (m) {
                    const int r = __ffs(m) - 1;     // owning lane of this row
                    m &= m - 1u;
                    const float xr = __shfl_sync(FULL, s ? x1 : x0, r);
                    const float dA = 1.0f - fabsf(xr - pc0);
                    const float dB = 1.0f - fabsf(xr - pc1);
                    const unsigned kA = ((t0 >> l) & 1u) ? 0u : __float_as_uint(dA);
                    const unsigned kB = ((t1 >> l) & 1u) ? 0u : __float_as_uint(dB);
                    const unsigned kw = __reduce_max_sync(FULL, kA > kB ? kA : kB);
                    const unsigned bA = __ballot_sync(FULL, kA == kw);
                    const unsigned bB = __ballot_sync(FULL, kB == kw);
                    const int j = bA ? (__ffs(bA) - 1) : (32 + __ffs(bB) - 1);
                    if (l == 0 && kw != 0u) {
                        const int row = r + (s << 5);
                        // key = (d desc, row asc); kw > 0 so key != 0.
                        atomicMax(&s_ck[w][j],
                            ((unsigned long long)kw << 6) |
                            (unsigned long long)(63 - row));
                    }
                }
            }
            __syncwarp();

            // Column accept: every proposed column takes its best proposer
            // (max d, lowest row) — exactly E = v*A*C mutual-best.
            unsigned nlo = 0u, nhi = 0u;
            bool acc0 = false, acc1 = false;
            {
                const unsigned long long k = s_ck[w][l];
                if (k) {
                    const int r = 63 - (int)(k & 63ULL);
                    s_perm[w][r] = l;
                    s_ck[w][l]   = 0ULL;
                    acc0 = true;
                    if (r < 32) nlo |= 1u << r; else nhi |= 1u << (r - 32);
                }
            }
            {
                const unsigned long long k = s_ck[w][l + 32];
                if (k) {
                    const int r = 63 - (int)(k & 63ULL);
                    s_perm[w][r]    = l + 32;
                    s_ck[w][l + 32] = 0ULL;
                    acc1 = true;
                    if (r < 32) nlo |= 1u << r; else nhi |= 1u << (r - 32);
                }
            }
            t0    |= __ballot_sync(FULL, acc0);
            t1    |= __ballot_sync(FULL, acc1);
            asgLo |= __reduce_or_sync(FULL, nlo);
            asgHi |= __reduce_or_sync(FULL, nhi);
            __syncwarp();
        }
    }

    __syncwarp();

    // --- Loss: lane handles rows l and l+32 against permuted prediction ---
    float loss = 0.0f;
    #pragma unroll
    for (int s = 0; s < 2; ++s) {
        const int    r   = l + (s << 5);
        const float  a   = s ? a1 : a0;
        const float  x   = s ? x1 : x0;
        const int    pi  = s_perm[w][r];
        const float* ypp = yp + (size_t)pi * FEAT;
        const float* ytr = yt + (size_t)r  * FEAT;

        const float d1 = x - ypp[1];
        const float d0 = a - ypp[0];
        loss += a * 5.0f * d1 * d1
              + a * d0 * d0
              + (1.0f - a) * 0.5f * d0 * d0;
        float s2 = 0.0f;
        #pragma unroll
        for (int f = 2; f < FEAT; ++f) {
            const float d = ytr[f] - ypp[f];
            s2 += d * d;
        }
        loss += a * s2;
    }

    // Deterministic warp butterfly reduce
    #pragma unroll
    for (int off = 16; off > 0; off >>= 1)
        loss += __shfl_xor_sync(FULL, loss, off);
    if (l == 0) s_wpart[w] = loss;
    __syncthreads();

    // Block partial + last-block fixed-order global reduction.
    if (threadIdx.x == 0) {
        g_blockpart[blockIdx.x] =
            s_wpart[0] + s_wpart[1] + s_wpart[2] + s_wpart[3];
        __threadfence();
        const int c = atomicAdd(&g_count, 1);
        s_flag = (c == GRID - 1);
    }
    __syncthreads();

    if (s_flag) {
        __shared__ float sred[TPB];
        const int t = threadIdx.x;
        float v = 0.0f;
        #pragma unroll
        for (int k = 0; k < GRID / TPB; ++k)
            v += g_blockpart[t + k * TPB];   // fixed order per thread
        sred[t] = v;
        __syncthreads();
        #pragma unroll
        for (int off = TPB / 2; off > 0; off >>= 1) {
            if (t < off) sred[t] += sred[t + off];
            __syncthreads();
        }
        if (t == 0) {
            out[0]  = sred[0];
            g_count = 0;                     // reset for next graph replay
        }
    }
}

extern "C" void kernel_launch(void* const* d_in, const int* in_sizes, int n_in,
                              void* d_out, int out_size)
{
    const float* y_true = (const float*)d_in[0];
    const float* y_pred = (const float*)d_in[1];
    float*       out    = (float*)d_out;

    spotting_kernel<<<GRID, TPB>>>(y_true, y_pred, out);
}

// round 9
// speedup vs baseline: 1.5708x; 1.5708x over previous
#include <cuda_runtime.h>
#include <cuda_bf16.h>

static constexpr int BATCH = 2048;
static constexpr int NSLOT = 64;
static constexpr int FEAT  = 19;
static constexpr int WPC   = 8;              // warps (=batches) per CTA
static constexpr int TPB   = 32 * WPC;       // 256
static constexpr int GRID  = BATCH / WPC;    // 256

__device__ float g_blockpart[GRID];
__device__ int   g_count = 0;                // self-resetting -> graph-replay safe

// One WARP per batch. Lane l owns rows {l, l+32} and columns {l, l+32}.
// Matching loop is pure warp-synchronous: no __syncthreads until the final
// reduction, so batches never wait on each other.
__global__ __launch_bounds__(TPB) void spotting_kernel(
    const float* __restrict__ y_true,
    const float* __restrict__ y_pred,
    float*       __restrict__ out)
{
    const unsigned FULL = 0xffffffffu;
    const int w = threadIdx.x >> 5;
    const int l = threadIdx.x & 31;
    const int b = blockIdx.x * WPC + w;

    __shared__ float              s_p[WPC][NSLOT];    // p_j; taken -> 1e30
    __shared__ unsigned long long s_ck[WPC][NSLOT];   // proposal mailbox
    __shared__ int                s_perm[WPC][NSLOT]; // row -> column (-1 free)
    __shared__ float              s_wpart[WPC];
    __shared__ int                s_flag;

    const float* yt = y_true + (size_t)b * NSLOT * FEAT;
    const float* yp = y_pred + (size_t)b * NSLOT * FEAT;

    const int r0 = l, r1 = l + 32;
    const float a0 = yt[r0 * FEAT + 0];
    const float x0 = yt[r0 * FEAT + 1];
    const float a1 = yt[r1 * FEAT + 0];
    const float x1 = yt[r1 * FEAT + 1];

    s_p[w][r0]    = yp[r0 * FEAT + 1];
    s_p[w][r1]    = yp[r1 * FEAT + 1];
    s_ck[w][r0]   = 0ULL;
    s_ck[w][r1]   = 0ULL;
    s_perm[w][r0] = -1;
    s_perm[w][r1] = -1;
    __syncwarp();

    #pragma unroll 1
    for (int phase = 0; phase < 2; ++phase) {
        const bool inp0 = (phase == 0) ? (a0 > 0.5f) : (a0 <= 0.5f);
        const bool inp1 = (phase == 0) ? (a1 > 0.5f) : (a1 <= 0.5f);

        // Bounded like the reference scan (length = n); each productive
        // round assigns >= 1 row so the bound never binds.
        #pragma unroll 1
        for (int iter = 0; iter < NSLOT; ++iter) {
            const bool act0 = inp0 && (s_perm[w][r0] < 0);
            const bool act1 = inp1 && (s_perm[w][r1] < 0);
            if (__ballot_sync(FULL, act0 || act1) == 0u) break;

            // R2-exact row argmax: d = 1 - |x - p_j|, strict '>' ascending,
            // 4 contiguous chains merged in ascending order (first-occurrence
            // tie-break == jnp.argmax). Taken cols (p=1e30) give d ~ -1e30,
            // never selected while a free column (d > 0) exists.
            #pragma unroll
            for (int s = 0; s < 2; ++s) {
                const bool  act = s ? act1 : act0;
                if (act) {
                    const float x = s ? x1 : x0;
                    float v0 = -3e38f, v1 = -3e38f, v2 = -3e38f, v3 = -3e38f;
                    int   j0 = 0,      j1 = 16,    j2 = 32,     j3 = 48;
                    #pragma unroll 8
                    for (int k = 0; k < 16; ++k) {
                        const float d0 = 1.0f - fabsf(x - s_p[w][k]);
                        const float d1 = 1.0f - fabsf(x - s_p[w][16 + k]);
                        const float d2 = 1.0f - fabsf(x - s_p[w][32 + k]);
                        const float d3 = 1.0f - fabsf(x - s_p[w][48 + k]);
                        if (d0 > v0) { v0 = d0; j0 = k; }
                        if (d1 > v1) { v1 = d1; j1 = 16 + k; }
                        if (d2 > v2) { v2 = d2; j2 = 32 + k; }
                        if (d3 > v3) { v3 = d3; j3 = 48 + k; }
                    }
                    if (v1 > v0) { v0 = v1; j0 = j1; }   // ascending merge:
                    if (v2 > v0) { v0 = v2; j0 = j2; }   // ties keep lower j
                    if (v3 > v0) { v0 = v3; j0 = j3; }

                    const int row = s ? r1 : r0;
                    // key = (d desc, row asc); v0 > 0 -> key != 0.
                    atomicMax(&s_ck[w][j0],
                        ((unsigned long long)__float_as_uint(v0) << 6) |
                        (unsigned long long)(63 - row));
                }
            }
            __syncwarp();

            // Column accept (lane owns cols l, l+32): a proposed column takes
            // its best proposer — exactly E = v*A*C (mutual best).
            #pragma unroll
            for (int s = 0; s < 2; ++s) {
                const int c = s ? r1 : r0;
                const unsigned long long k = s_ck[w][c];
                if (k) {
                    const int r = 63 - (int)(k & 63ULL);
                    s_perm[w][r] = c;
                    s_p[w][c]    = 1e30f;   // remove column
                    s_ck[w][c]   = 0ULL;
                }
            }
            __syncwarp();
        }
    }

    // --- Loss: lane handles rows l, l+32 against permuted prediction ---
    float loss = 0.0f;
    #pragma unroll
    for (int s = 0; s < 2; ++s) {
        const int    r   = s ? r1 : r0;
        const float  a   = s ? a1 : a0;
        const float  x   = s ? x1 : x0;
        const int    pi  = s_perm[w][r];
        const float* ypp = yp + (size_t)pi * FEAT;
        const float* ytr = yt + (size_t)r  * FEAT;

        const float d1 = x - ypp[1];
        const float d0 = a - ypp[0];
        loss += a * 5.0f * d1 * d1
              + a * d0 * d0
              + (1.0f - a) * 0.5f * d0 * d0;
        float s2 = 0.0f;
        #pragma unroll
        for (int f = 2; f < FEAT; ++f) {
            const float d = ytr[f] - ypp[f];
            s2 += d * d;
        }
        loss += a * s2;
    }

    // Deterministic warp butterfly reduce
    #pragma unroll
    for (int off = 16; off > 0; off >>= 1)
        loss += __shfl_xor_sync(FULL, loss, off);
    if (l == 0) s_wpart[w] = loss;
    __syncthreads();

    // Block partial + last-block fixed-order global reduction.
    if (threadIdx.x == 0) {
        float v = 0.0f;
        #pragma unroll
        for (int k = 0; k < WPC; ++k) v += s_wpart[k];
        g_blockpart[blockIdx.x] = v;
        __threadfence();
        const int c = atomicAdd(&g_count, 1);
        s_flag = (c == GRID - 1);
    }
    __syncthreads();

    if (s_flag) {
        __shared__ float sred[GRID];
        const int t = threadIdx.x;
        sred[t] = g_blockpart[t];            // GRID == TPB == 256
        __syncthreads();
        #pragma unroll
        for (int off = GRID / 2; off > 0; off >>= 1) {
            if (t < off) sred[t] += sred[t + off];
            __syncthreads();
        }
        if (t == 0) {
            out[0]  = sred[0];
            g_count = 0;                     // reset for next graph replay
        }
    }
}

extern "C" void kernel_launch(void* const* d_in, const int* in_sizes, int n_in,
                              void* d_out, int out_size)
{
    const float* y_true = (const float*)d_in[0];
    const float* y_pred = (const float*)d_in[1];
    float*       out    = (float*)d_out;

    spotting_kernel<<<GRID, TPB>>>(y_true, y_pred, out);
}

// round 10
// speedup vs baseline: 2.1188x; 1.3489x over previous
#include <cuda_runtime.h>
#include <cuda_bf16.h>

static constexpr int BATCH = 2048;
static constexpr int NSLOT = 64;
static constexpr int FEAT  = 19;
static constexpr int WPC   = 4;              // warps (=batches) per CTA
static constexpr int TPB   = 32 * WPC;       // 128
static constexpr int GRID  = BATCH / WPC;    // 512

__device__ float g_blockpart[GRID];
__device__ int   g_count = 0;                // self-resetting -> graph-replay safe

using ull = unsigned long long;

// One WARP per batch. Columns sorted once by (p, j); row argmax over free
// columns = nearest free p to x, found by bit-walks over a 64-bit free mask.
// 2 candidates per side + packed-key compare reproduce jnp.argmax ties exactly
// (incl. equal-p pairs and single fl(1-m) rounding merges).
__global__ __launch_bounds__(TPB) void spotting_kernel(
    const float* __restrict__ y_true,
    const float* __restrict__ y_pred,
    float*       __restrict__ out)
{
    const unsigned FULL = 0xffffffffu;
    const int w = threadIdx.x >> 5;
    const int l = threadIdx.x & 31;
    const int b = blockIdx.x * WPC + w;

    __shared__ ull   s_ck[WPC][NSLOT];    // unsorted keys during setup, then mailbox
    __shared__ ull   s_key[WPC][NSLOT];   // sorted (p_bits<<6)|j
    __shared__ int   s_pos[WPC][NSLOT];   // original col -> sorted position
    __shared__ int   s_perm[WPC][NSLOT];  // row -> column (-1 free)
    __shared__ ull   s_free[WPC];         // free mask over sorted positions
    __shared__ float s_wpart[WPC];
    __shared__ int   s_flag;

    const float* yt = y_true + (size_t)b * NSLOT * FEAT;
    const float* yp = y_pred + (size_t)b * NSLOT * FEAT;

    const int r0 = l, r1 = l + 32;
    const float a0 = yt[r0 * FEAT + 0];
    const float x0 = yt[r0 * FEAT + 1];
    const float a1 = yt[r1 * FEAT + 0];
    const float x1 = yt[r1 * FEAT + 1];

    // --- setup: keys, rank-sort, positions ---
    {
        const float p0 = yp[r0 * FEAT + 1];
        const float p1 = yp[r1 * FEAT + 1];
        s_ck[w][r0]   = ((ull)__float_as_uint(p0) << 6) | (ull)r0;
        s_ck[w][r1]   = ((ull)__float_as_uint(p1) << 6) | (ull)r1;
        s_perm[w][r0] = -1;
        s_perm[w][r1] = -1;
    }
    __syncwarp();
    #pragma unroll
    for (int s = 0; s < 2; ++s) {
        const int c = s ? r1 : r0;
        const ull mykey = s_ck[w][c];
        int rank = 0;
        #pragma unroll 8
        for (int j = 0; j < NSLOT; ++j) rank += (s_ck[w][j] < mykey);
        s_key[w][rank] = mykey;           // keys unique -> perfect scatter
        s_pos[w][c]    = rank;
    }
    __syncwarp();
    s_ck[w][r0] = 0ULL;                   // becomes the proposal mailbox
    s_ck[w][r1] = 0ULL;
    if (l == 0) s_free[w] = ~0ULL;
    __syncwarp();

    // Binary search: posX = #\{p < x\} over sorted keys (p bits monotone).
    auto lower_pos = [&](float x) -> int {
        const unsigned xb = __float_as_uint(x);
        int pos = 0;
        #pragma unroll
        for (int s = 32; s; s >>= 1) {
            const unsigned pb = (unsigned)(s_key[w][pos + s - 1] >> 6);
            if (pb < xb) pos += s;
        }
        return pos;
    };
    const int pos0 = lower_pos(x0);
    const int pos1 = lower_pos(x1);

    // Candidate eval + proposal. best = max over candidates of
    // (d_bits << 6) | (63 - j): max d, then lowest j (== jnp.argmax ties).
    auto propose = [&](float x, int pos, int row, ull freem) {
        ull best = 0ULL;
        auto consider = [&](int c) {
            const ull   key = s_key[w][c];
            const float p   = __uint_as_float((unsigned)(key >> 6));
            const int   j   = (int)(key & 63ULL);
            const float d   = 1.0f - fabsf(x - p);
            const ull   sk  = ((ull)__float_as_uint(d) << 6) | (ull)(63 - j);
            if (sk > best) best = sk;
        };
        const ull lowm  = (pos >= 64) ? ~0ULL : ((1ULL << pos) - 1ULL);
        ull below = freem & lowm;
        ull above = freem & ~lowm;
        if (below) {                       // 2 nearest free below
            int c = 63 - __clzll((long long)below);
            below &= ~(1ULL << c);
            consider(c);
            if (below) consider(63 - __clzll((long long)below));
        }
        if (above) {                       // 2 nearest free above
            int c = __ffsll((long long)above) - 1;
            above &= above - 1;
            consider(c);
            if (above) consider(__ffsll((long long)above) - 1);
        }
        const int jb = 63 - (int)(best & 63ULL);
        // mailbox key: (d desc, row asc); d > 0 so key != 0.
        atomicMax(&s_ck[w][jb], (best & ~63ULL) | (ull)(63 - row));
    };

    #pragma unroll 1
    for (int phase = 0; phase < 2; ++phase) {
        const bool inp0 = (phase == 0) ? (a0 > 0.5f) : (a0 <= 0.5f);
        const bool inp1 = (phase == 0) ? (a1 > 0.5f) : (a1 <= 0.5f);

        // Bounded like the reference scan; each productive round assigns >= 1.
        #pragma unroll 1
        for (int iter = 0; iter < NSLOT; ++iter) {
            const bool act0 = inp0 && (s_perm[w][r0] < 0);
            const bool act1 = inp1 && (s_perm[w][r1] < 0);
            if (__ballot_sync(FULL, act0 || act1) == 0u) break;

            const ull freem = s_free[w];
            if (act0) propose(x0, pos0, r0, freem);
            if (act1) propose(x1, pos1, r1, freem);
            __syncwarp();

            // Column accept: proposed column takes best proposer (E = v*A*C).
            #pragma unroll
            for (int s = 0; s < 2; ++s) {
                const int c = s ? r1 : r0;
                const ull k = s_ck[w][c];
                if (k) {
                    const int r = 63 - (int)(k & 63ULL);
                    s_perm[w][r] = c;
                    s_ck[w][c]   = 0ULL;
                    atomicAnd(&s_free[w], ~(1ULL << s_pos[w][c]));
                }
            }
            __syncwarp();
        }
    }

    // --- Loss: lane handles rows l, l+32 against permuted prediction ---
    float loss = 0.0f;
    #pragma unroll
    for (int s = 0; s < 2; ++s) {
        const int    r   = s ? r1 : r0;
        const float  a   = s ? a1 : a0;
        const float  x   = s ? x1 : x0;
        const int    pi  = s_perm[w][r];
        const float* ypp = yp + (size_t)pi * FEAT;
        const float* ytr = yt + (size_t)r  * FEAT;

        const float d1 = x - ypp[1];
        const float d0 = a - ypp[0];
        loss += a * 5.0f * d1 * d1
              + a * d0 * d0
              + (1.0f - a) * 0.5f * d0 * d0;
        float s2 = 0.0f;
        #pragma unroll
        for (int f = 2; f < FEAT; ++f) {
            const float d = ytr[f] - ypp[f];
            s2 += d * d;
        }
        loss += a * s2;
    }

    #pragma unroll
    for (int off = 16; off > 0; off >>= 1)
        loss += __shfl_xor_sync(FULL, loss, off);
    if (l == 0) s_wpart[w] = loss;
    __syncthreads();

    if (threadIdx.x == 0) {
        g_blockpart[blockIdx.x] =
            s_wpart[0] + s_wpart[1] + s_wpart[2] + s_wpart[3];
        __threadfence();
        const int c = atomicAdd(&g_count, 1);
        s_flag = (c == GRID - 1);
    }
    __syncthreads();

    if (s_flag) {
        __shared__ float sred[TPB];
        const int t = threadIdx.x;
        float v = 0.0f;
        #pragma unroll
        for (int k = 0; k < GRID / TPB; ++k)
            v += g_blockpart[t + k * TPB];   // fixed order per thread
        sred[t] = v;
        __syncthreads();
        #pragma unroll
        for (int off = TPB / 2; off > 0; off >>= 1) {
            if (t < off) sred[t] += sred[t + off];
            __syncthreads();
        }
        if (t == 0) {
            out[0]  = sred[0];
            g_count = 0;                     // reset for next graph replay
        }
    }
}

extern "C" void kernel_launch(void* const* d_in, const int* in_sizes, int n_in,
                              void* d_out, int out_size)
{
    const float* y_true = (const float*)d_in[0];
    const float* y_pred = (const float*)d_in[1];
    float*       out    = (float*)d_out;

    spotting_kernel<<<GRID, TPB>>>(y_true, y_pred, out);
}

// round 11
// speedup vs baseline: 2.4441x; 1.1535x over previous
#include <cuda_runtime.h>
#include <cuda_bf16.h>

static constexpr int BATCH = 2048;
static constexpr int NSLOT = 64;
static constexpr int FEAT  = 19;
static constexpr int ROWF  = NSLOT * FEAT;       // 1216 floats per tensor/batch
static constexpr int VEC4  = ROWF / 4;           // 304 float4
static constexpr int WPC   = 4;                  // warps (=batches) per CTA
static constexpr int TPB   = 32 * WPC;           // 128
static constexpr int GRID  = BATCH / WPC;        // 512

__device__ float g_blockpart[GRID];
__device__ int   g_count = 0;                    // self-resetting, replay-safe

using ull = unsigned long long;

// Replicated-register 64-bit OR across the warp (2x hardware redux).
__device__ __forceinline__ ull warp_or64(ull v) {
    const unsigned lo = __reduce_or_sync(0xffffffffu, (unsigned)v);
    const unsigned hi = __reduce_or_sync(0xffffffffu, (unsigned)(v >> 32));
    return ((ull)hi << 32) | (ull)lo;
}

// One WARP per batch. Sorted nearest-free-neighbor matching (R10-exact),
// with all tensor data staged coalesced into smem and loop state in registers.
__global__ __launch_bounds__(TPB) void spotting_kernel(
    const float* __restrict__ y_true,
    const float* __restrict__ y_pred,
    float*       __restrict__ out)
{
    const unsigned FULL = 0xffffffffu;
    const int w = threadIdx.x >> 5;
    const int l = threadIdx.x & 31;
    const int b = blockIdx.x * WPC + w;

    __shared__ alignas(16) float s_yt[WPC][ROWF];
    __shared__ alignas(16) float s_yp[WPC][ROWF];
    __shared__ ull   s_ck[WPC][NSLOT];    // sort keys during setup, then mailbox
    __shared__ ull   s_key[WPC][NSLOT];   // sorted (p_bits<<6)|j
    __shared__ int   s_perm[WPC][NSLOT];  // row -> column
    __shared__ float s_wpart[WPC];
    __shared__ int   s_flag;

    // ---- coalesced stage of this batch (10 x LDG.128 per lane/tensor) ----
    {
        const float4* gt = reinterpret_cast<const float4*>(y_true + (size_t)b * ROWF);
        const float4* gp = reinterpret_cast<const float4*>(y_pred + (size_t)b * ROWF);
        float4* dt = reinterpret_cast<float4*>(s_yt[w]);
        float4* dp = reinterpret_cast<float4*>(s_yp[w]);
        #pragma unroll
        for (int k = l; k < VEC4; k += 32) { dt[k] = gt[k]; dp[k] = gp[k]; }
    }
    __syncwarp();

    const int r0 = l, r1 = l + 32;
    const float a0 = s_yt[w][r0 * FEAT + 0];
    const float x0 = s_yt[w][r0 * FEAT + 1];
    const float a1 = s_yt[w][r1 * FEAT + 0];
    const float x1 = s_yt[w][r1 * FEAT + 1];

    // ---- setup: keys, rank-sort, own-column sorted positions ----
    s_ck[w][r0] = ((ull)__float_as_uint(s_yp[w][r0 * FEAT + 1]) << 6) | (ull)r0;
    s_ck[w][r1] = ((ull)__float_as_uint(s_yp[w][r1 * FEAT + 1]) << 6) | (ull)r1;
    __syncwarp();
    int cpos0, cpos1;
    #pragma unroll
    for (int s = 0; s < 2; ++s) {
        const int c = s ? r1 : r0;
        const ull mykey = s_ck[w][c];
        int rank = 0;
        #pragma unroll 8
        for (int j = 0; j < NSLOT; ++j) rank += (s_ck[w][j] < mykey);
        s_key[w][rank] = mykey;            // unique keys -> perfect scatter
        if (s) cpos1 = rank; else cpos0 = rank;
    }
    __syncwarp();
    s_ck[w][r0] = 0ULL;                    // becomes the proposal mailbox
    s_ck[w][r1] = 0ULL;
    __syncwarp();

    // Binary search: pos = #\{p < x\} over sorted keys (p bits monotone).
    auto lower_pos = [&](float x) -> int {
        const unsigned xb = __float_as_uint(x);
        int pos = 0;
        #pragma unroll
        for (int s = 32; s; s >>= 1) {
            const unsigned pb = (unsigned)(s_key[w][pos + s - 1] >> 6);
            if (pb < xb) pos += s;
        }
        return pos;
    };
    const int pos0 = lower_pos(x0);
    const int pos1 = lower_pos(x1);

    // Candidate eval + proposal: best = max over <=4 nearest-free candidates
    // of (d_bits << 6) | (63 - j) -> max d, lowest j (== jnp.argmax ties).
    auto propose = [&](float x, int pos, int row, ull freem) {
        ull best = 0ULL;
        auto consider = [&](int c) {
            const ull   key = s_key[w][c];
            const float p   = __uint_as_float((unsigned)(key >> 6));
            const int   j   = (int)(key & 63ULL);
            const float d   = 1.0f - fabsf(x - p);
            const ull   sk  = ((ull)__float_as_uint(d) << 6) | (ull)(63 - j);
            if (sk > best) best = sk;
        };
        const ull lowm = (pos >= 64) ? ~0ULL : ((1ULL << pos) - 1ULL);
        ull below = freem & lowm;
        ull above = freem & ~lowm;
        if (below) {                        // 2 nearest free below
            int c = 63 - __clzll((long long)below);
            below &= ~(1ULL << c);
            consider(c);
            if (below) consider(63 - __clzll((long long)below));
        }
        if (above) {                        // 2 nearest free above
            int c = __ffsll((long long)above) - 1;
            above &= above - 1;
            consider(c);
            if (above) consider(__ffsll((long long)above) - 1);
        }
        const int jb = 63 - (int)(best & 63ULL);
        // mailbox key: (d desc, row asc); d > 0 so key != 0.
        atomicMax(&s_ck[w][jb], (best & ~63ULL) | (ull)(63 - row));
    };

    ull asg   = 0ULL;    // assigned rows (replicated register)
    ull freem = ~0ULL;   // free columns in sorted positions (replicated)

    #pragma unroll 1
    for (int phase = 0; phase < 2; ++phase) {
        const bool inp0 = (phase == 0) ? (a0 > 0.5f) : (a0 <= 0.5f);
        const bool inp1 = (phase == 0) ? (a1 > 0.5f) : (a1 <= 0.5f);

        // Bounded like the reference scan; each productive round assigns >=1.
        #pragma unroll 1
        for (int iter = 0; iter < NSLOT; ++iter) {
            const bool act0 = inp0 && !((asg >> r0) & 1ULL);
            const bool act1 = inp1 && !((asg >> r1) & 1ULL);
            if (__ballot_sync(FULL, act0 || act1) == 0u) break;

            if (act0) propose(x0, pos0, r0, freem);
            if (act1) propose(x1, pos1, r1, freem);
            __syncwarp();

            // Column accept: proposed column takes its best proposer
            // (max d, lowest row) — exactly E = v*A*C mutual-best.
            ull nasg = 0ULL, ntaken = 0ULL;
            #pragma unroll
            for (int s = 0; s < 2; ++s) {
                const int c = s ? r1 : r0;
                const ull k = s_ck[w][c];
                if (k) {
                    const int r = 63 - (int)(k & 63ULL);
                    s_perm[w][r] = c;
                    s_ck[w][c]   = 0ULL;
                    nasg   |= 1ULL << r;
                    ntaken |= 1ULL << (s ? cpos1 : cpos0);
                }
            }
            asg   |= warp_or64(nasg);
            freem &= ~warp_or64(ntaken);
            __syncwarp();
        }
    }

    // --- Loss: lane handles rows l, l+32; gather from staged smem ---
    // (row stride 19 is coprime to 32 banks -> conflict-free gather)
    float loss = 0.0f;
    #pragma unroll
    for (int s = 0; s < 2; ++s) {
        const int    r   = s ? r1 : r0;
        const float  a   = s ? a1 : a0;
        const float  x   = s ? x1 : x0;
        const int    pi  = s_perm[w][r];
        const float* ypp = &s_yp[w][pi * FEAT];
        const float* ytr = &s_yt[w][r  * FEAT];

        const float d1 = x - ypp[1];
        const float d0 = a - ypp[0];
        loss += a * 5.0f * d1 * d1
              + a * d0 * d0
              + (1.0f - a) * 0.5f * d0 * d0;
        float s2 = 0.0f;
        #pragma unroll
        for (int f = 2; f < FEAT; ++f) {
            const float d = ytr[f] - ypp[f];
            s2 += d * d;
        }
        loss += a * s2;
    }

    #pragma unroll
    for (int off = 16; off > 0; off >>= 1)
        loss += __shfl_xor_sync(FULL, loss, off);
    if (l == 0) s_wpart[w] = loss;
    __syncthreads();

    if (threadIdx.x == 0) {
        g_blockpart[blockIdx.x] =
            s_wpart[0] + s_wpart[1] + s_wpart[2] + s_wpart[3];
        __threadfence();
        const int c = atomicAdd(&g_count, 1);
        s_flag = (c == GRID - 1);
    }
    __syncthreads();

    if (s_flag) {
        __shared__ float sred[TPB];
        const int t = threadIdx.x;
        float v = 0.0f;
        #pragma unroll
        for (int k = 0; k < GRID / TPB; ++k)
            v += g_blockpart[t + k * TPB];   // fixed order per thread
        sred[t] = v;
        __syncthreads();
        #pragma unroll
        for (int off = TPB / 2; off > 0; off >>= 1) {
            if (t < off) sred[t] += sred[t + off];
            __syncthreads();
        }
        if (t == 0) {
            out[0]  = sred[0];
            g_count = 0;                     // reset for next graph replay
        }
    }
}

extern "C" void kernel_launch(void* const* d_in, const int* in_sizes, int n_in,
                              void* d_out, int out_size)
{
    const float* y_true = (const float*)d_in[0];
    const float* y_pred = (const float*)d_in[1];
    float*       out    = (float*)d_out;

    spotting_kernel<<<GRID, TPB>>>(y_true, y_pred, out);
}